// round 16
// baseline (speedup 1.0000x reference)
#include <cuda_runtime.h>
#include <cuda_fp16.h>
#include <cstdint>

#define BB 4
#define TT 1024
#define DD 1024
#define HH 16
#define HD 64
#define SC 3072
#define SF 4096

typedef __half fp16;
typedef __half2 fp162;

__device__ fp16 g_xh[(size_t)BB * TT * DD];
__device__ fp16 g_wth[4ull * DD * DD];           // transposed weights [w][n][k]
__device__ fp16 g_qh[(size_t)BB * HH * TT * HD]; // q pre-scaled by 0.125*log2(e)
__device__ fp16 g_kh[(size_t)BB * HH * SF * HD];
__device__ fp16 g_vth[(size_t)BB * HH * HD * SF];
__device__ fp16 g_ah[(size_t)BB * TT * DD];      // attn out

__device__ __forceinline__ uint32_t smem_u32(const void* p) {
    return (uint32_t)__cvta_generic_to_shared(p);
}
__device__ __forceinline__ void ldsm4(uint32_t (&r)[4], const void* p) {
    asm volatile("ldmatrix.sync.aligned.m8n8.x4.shared.b16 {%0,%1,%2,%3}, [%4];"
        : "=r"(r[0]), "=r"(r[1]), "=r"(r[2]), "=r"(r[3]) : "r"(smem_u32(p)));
}
__device__ __forceinline__ void mma16816h(float (&c)[4], const uint32_t (&a)[4],
                                          uint32_t b0, uint32_t b1) {
    asm volatile(
        "mma.sync.aligned.m16n8k16.row.col.f32.f16.f16.f32 "
        "{%0,%1,%2,%3},{%4,%5,%6,%7},{%8,%9},{%0,%1,%2,%3};"
        : "+f"(c[0]), "+f"(c[1]), "+f"(c[2]), "+f"(c[3])
        : "r"(a[0]), "r"(a[1]), "r"(a[2]), "r"(a[3]), "r"(b0), "r"(b1));
}
__device__ __forceinline__ uint32_t packh(float x, float y) {
    fp162 t = __floats2half2_rn(x, y);
    return *reinterpret_cast<uint32_t*>(&t);
}
__device__ __forceinline__ float ex2f(float x) {
    float r;
    asm("ex2.approx.f32 %0, %1;" : "=f"(r) : "f"(x));
    return r;
}
__device__ __forceinline__ void cpa16(uint32_t dst, const void* src) {
    asm volatile("cp.async.cg.shared.global [%0], [%1], 16;"
        :: "r"(dst), "l"(__cvta_generic_to_global(src)));
}

// ---------------- merged x + W conversion -------------------------------------
// blocks [0,4096): x -> fp16 ; [4096,8192): weight transpose+convert
__global__ void conv_xw(const float4* __restrict__ x,
                        const float* __restrict__ Wq, const float* __restrict__ Wk,
                        const float* __restrict__ Wv, const float* __restrict__ Wo) {
    __shared__ float t[32][33];
    const int blk = blockIdx.x, tid = threadIdx.x;
    if (blk < 4096) {
        int i = blk * 256 + tid;
        float4 v = x[i];
        reinterpret_cast<fp162*>(g_xh)[2 * i]     = __floats2half2_rn(v.x, v.y);
        reinterpret_cast<fp162*>(g_xh)[2 * i + 1] = __floats2half2_rn(v.z, v.w);
    } else {
        int wb = blk - 4096;
        int z = wb >> 10, rem = wb & 1023;
        int n0 = (rem & 31) * 32, k0 = (rem >> 5) * 32;
        const float* W = (z == 0) ? Wq : (z == 1) ? Wk : (z == 2) ? Wv : Wo;
        int tx = tid & 31, ty = tid >> 5;   // ty 0..7
        #pragma unroll
        for (int r = 0; r < 32; r += 8)
            t[ty + r][tx] = W[(size_t)(k0 + ty + r) * DD + n0 + tx];
        __syncthreads();
        size_t base = (size_t)z * DD * DD;
        #pragma unroll
        for (int r = 0; r < 32; r += 8)
            g_wth[base + (size_t)(n0 + ty + r) * DD + k0 + tx] =
                __float2half_rn(t[tx][ty + r]);
    }
}

// ------- fp16 HMMA GEMM core: 128 thr, 4 warps x (64x64), BK=32, cp.async ----
__device__ __forceinline__ void gemm_fill(fp16 (&As)[2][128][40], fp16 (&Bs)[2][128][40],
                                          const fp16* __restrict__ Ah,
                                          const fp16* __restrict__ Bh,
                                          int bm, int bn, int k0, int buf, int tid) {
    #pragma unroll
    for (int it = 0; it < 4; it++) {
        int idx = it * 128 + tid;        // 0..511
        int r = idx >> 2, cg = (idx & 3) * 8;
        cpa16(smem_u32(&As[buf][r][cg]), Ah + (size_t)(bm + r) * DD + k0 + cg);
        cpa16(smem_u32(&Bs[buf][r][cg]), Bh + (size_t)(bn + r) * DD + k0 + cg);
    }
}

__device__ __forceinline__ void gemm_core(fp16 (&As)[2][128][40], fp16 (&Bs)[2][128][40],
                                          const fp16* __restrict__ Ah,
                                          const fp16* __restrict__ Bh,
                                          int bm, int bn, float (&c)[4][8][4]) {
    const int tid  = threadIdx.x;
    const int lane = tid & 31, wid = tid >> 5;
    const int wm = (wid & 1) * 64, wn = (wid >> 1) * 64;
    const int ar = lane & 15, akk = (lane >> 4) * 8;
    const int br = (lane & 7) + ((lane >> 4) << 3), bkk = ((lane >> 3) & 1) * 8;

    #pragma unroll
    for (int mt = 0; mt < 4; mt++)
        #pragma unroll
        for (int nt = 0; nt < 8; nt++)
            #pragma unroll
            for (int e = 0; e < 4; e++) c[mt][nt][e] = 0.0f;

    gemm_fill(As, Bs, Ah, Bh, bm, bn, 0, 0, tid);
    asm volatile("cp.async.commit_group;");

    int buf = 0;
    #pragma unroll 1
    for (int ch = 0; ch < 32; ch++) {
        __syncthreads();
        if (ch < 31) {
            gemm_fill(As, Bs, Ah, Bh, bm, bn, (ch + 1) << 5, buf ^ 1, tid);
            asm volatile("cp.async.commit_group;");
            asm volatile("cp.async.wait_group 1;");
        } else {
            asm volatile("cp.async.wait_group 0;");
        }
        __syncthreads();

        #pragma unroll
        for (int kc2 = 0; kc2 < 2; kc2++) {
            uint32_t a[4][4], bfr[4][4];
            #pragma unroll
            for (int mt = 0; mt < 4; mt++)
                ldsm4(a[mt], &As[buf][wm + mt * 16 + ar][kc2 * 16 + akk]);
            #pragma unroll
            for (int np = 0; np < 4; np++)
                ldsm4(bfr[np], &Bs[buf][wn + np * 16 + br][kc2 * 16 + bkk]);
            #pragma unroll
            for (int mt = 0; mt < 4; mt++)
                #pragma unroll
                for (int nt = 0; nt < 8; nt++) {
                    int np = nt >> 1, pi = (nt & 1) * 2;
                    mma16816h(c[mt][nt], a[mt], bfr[np][pi], bfr[np][pi + 1]);
                }
        }
        buf ^= 1;
    }
}

// Q scale = 0.125 (hd^-0.5 folded) * log2(e)
#define QSCALE 0.18033688011112042f

// Fused kernel: z<3 = GEMM tiles; z>=3 = cache conversion blocks (overlap).
__global__ __launch_bounds__(128, 2) void gemm_qkv(
    const float* __restrict__ bq, const float* __restrict__ bv,
    const float4* __restrict__ kc4, const float* __restrict__ vc,
    float* __restrict__ kout, float* __restrict__ vout) {
    __shared__ __align__(16) fp16 As[2][128][40];
    __shared__ __align__(16) fp16 Bs[2][128][40];
    __shared__ float t[32][33];

    const int tid = threadIdx.x;

    if (blockIdx.z >= 3) {
        int cid = (int)(blockIdx.z - 3) * 256 + blockIdx.y * 8 + blockIdx.x;
        if (cid < 3072) {
            #pragma unroll
            for (int it = 0; it < 8; it++) {
                int i = cid * 1024 + it * 128 + tid;
                const int per_b = SC * 256;
                int b = i / per_b, r = i - b * per_b;
                int sr = r >> 8, n4 = r & 255;
                float4 v = kc4[i];
                *reinterpret_cast<float4*>(&kout[(((size_t)b * SF + sr) * 256 + n4) * 4]) = v;
                int n = n4 * 4, h = n >> 6, d = n & 63;
                size_t o = ((size_t)(b * HH + h) * SF + sr) * HD + d;
                *reinterpret_cast<fp162*>(&g_kh[o])     = __floats2half2_rn(v.x, v.y);
                *reinterpret_cast<fp162*>(&g_kh[o + 2]) = __floats2half2_rn(v.z, v.w);
            }
        } else {
            int vb = cid - 3072;                 // [0, 12288)
            int xst = vb % 96;
            int y   = (vb / 96) % 32;
            int b   = vb / 3072;
            int st = xst * 32, h = y >> 1, d0 = (y & 1) * 32;
            int tx = tid & 31, ty = tid >> 5;    // ty 0..3
            #pragma unroll
            for (int r = 0; r < 32; r += 4) {
                float v = vc[(size_t)b * SC * DD + (size_t)(st + ty + r) * DD + h * HD + d0 + tx];
                t[ty + r][tx] = v;
                vout[((size_t)b * SF + st + ty + r) * DD + h * HD + d0 + tx] = v;
            }
            __syncthreads();
            #pragma unroll
            for (int r = 0; r < 32; r += 4) {
                size_t o = ((size_t)(b * HH + h) * HD + d0 + ty + r) * SF + st + tx;
                g_vth[o] = __float2half_rn(t[tx][ty + r]);
            }
        }
        return;
    }

    const int z = blockIdx.z;
    const int bm = blockIdx.y * 128, bn = blockIdx.x * 128;
    float c[4][8][4];
    gemm_core(As, Bs, g_xh, g_wth + (size_t)z * DD * DD, bm, bn, c);

    const int lane = tid & 31, wid = tid >> 5;
    const int wm = (wid & 1) * 64, wn = (wid >> 1) * 64;
    const int g = lane >> 2, tg = lane & 3;

    #pragma unroll
    for (int mt = 0; mt < 4; mt++)
        #pragma unroll
        for (int nt = 0; nt < 8; nt++)
            #pragma unroll
            for (int hf = 0; hf < 2; hf++) {
                int row = bm + wm + mt * 16 + g + hf * 8;
                int col = bn + wn + nt * 8 + tg * 2;
                float v0 = c[mt][nt][hf * 2], v1 = c[mt][nt][hf * 2 + 1];
                int b = row >> 10, tt = row & 1023;
                int h = col >> 6, d = col & 63;
                if (z == 0) {
                    v0 = (v0 + bq[col]) * QSCALE;
                    v1 = (v1 + bq[col + 1]) * QSCALE;
                    size_t o = ((size_t)(b * HH + h) * TT + tt) * HD + d;
                    *reinterpret_cast<fp162*>(&g_qh[o]) = __floats2half2_rn(v0, v1);
                } else if (z == 1) {
                    *(float2*)&kout[((size_t)b * SF + SC + tt) * DD + col] = make_float2(v0, v1);
                    size_t o = ((size_t)(b * HH + h) * SF + SC + tt) * HD + d;
                    *reinterpret_cast<fp162*>(&g_kh[o]) = __floats2half2_rn(v0, v1);
                } else {
                    v0 += bv[col]; v1 += bv[col + 1];
                    *(float2*)&vout[((size_t)b * SF + SC + tt) * DD + col] = make_float2(v0, v1);
                    // fold V-transpose: g_vth[b,h][d][SC+tt]
                    size_t vo = ((size_t)(b * HH + h) * HD + d) * SF + SC + tt;
                    g_vth[vo]      = __float2half_rn(v0);
                    g_vth[vo + SF] = __float2half_rn(v1);
                }
            }
}

__global__ __launch_bounds__(128, 2) void gemm_o(const float* __restrict__ bo,
                                                 float* __restrict__ out) {
    __shared__ __align__(16) fp16 As[2][128][40];
    __shared__ __align__(16) fp16 Bs[2][128][40];

    const int bm = blockIdx.y * 128, bn = blockIdx.x * 128;
    float c[4][8][4];
    gemm_core(As, Bs, g_ah, g_wth + 3ull * DD * DD, bm, bn, c);

    const int tid = threadIdx.x, lane = tid & 31, wid = tid >> 5;
    const int wm = (wid & 1) * 64, wn = (wid >> 1) * 64;
    const int g = lane >> 2, tg = lane & 3;

    #pragma unroll
    for (int mt = 0; mt < 4; mt++)
        #pragma unroll
        for (int nt = 0; nt < 8; nt++)
            #pragma unroll
            for (int hf = 0; hf < 2; hf++) {
                int row = bm + wm + mt * 16 + g + hf * 8;
                int col = bn + wn + nt * 8 + tg * 2;
                float v0 = c[mt][nt][hf * 2] + bo[col];
                float v1 = c[mt][nt][hf * 2 + 1] + bo[col + 1];
                *(float2*)&out[(size_t)row * DD + col] = make_float2(v0, v1);
            }
}

// -------- FlashAttention: 128-row q tiles, 4 warps x 32 rows, 3-stage pipe ---
// dynamic smem: 3 buffers x (Ksh,Vsh) x [64][72] fp16 = 55296 B
__global__ __launch_bounds__(128) void attn_mma() {
    extern __shared__ __align__(16) fp16 dsm[];

    const int tid = threadIdx.x, lane = tid & 31, wid = tid >> 5;
    const int qi = 7 - blockIdx.x;           // heavy tiles first (qi 0..7)
    const int h = blockIdx.y, b = blockIdx.z;
    const int qb = qi * 128;
    const int g = lane >> 2, tg = lane & 3;
    const int ar = lane & 15, akk = (lane >> 4) * 8;
    const int br = (lane & 7) + ((lane >> 4) << 3), bkk = ((lane >> 3) & 1) * 8;
    const float NEGINF = __int_as_float(0xff800000);
    const uint32_t ones = (lane < 4) ? 0x3C003C00u : 0u;

    const size_t kbase = (size_t)(b * HH + h) * SF * HD;
    const size_t vbase = (size_t)(b * HH + h) * HD * SF;
    const uint32_t smem0 = smem_u32(dsm);

    // tile iterator with mask-skip: skip si in [2qi+2, 16)
    int t0 = 0;
    int n1 = (1 < 16 && 1 >= 2 * qi + 2) ? 16 : 1;
    int ahead = (n1 + 1 < 16 && n1 + 1 >= 2 * qi + 2) ? 16 : n1 + 1;

    #pragma unroll
    for (int p = 0; p < 4; p++) {
        int idx = p * 1024 + tid * 8;
        int r = idx >> 6, cc = idx & 63;
        uint32_t doff = (uint32_t)(r * 144 + cc * 2);
        cpa16(smem0 + doff,        g_kh  + kbase + (size_t)(t0 * 64 + r) * HD + cc);
        cpa16(smem0 + 9216 + doff, g_vth + vbase + (size_t)r * SF + t0 * 64 + cc);
    }
    asm volatile("cp.async.commit_group;");
    #pragma unroll
    for (int p = 0; p < 4; p++) {
        int idx = p * 1024 + tid * 8;
        int r = idx >> 6, cc = idx & 63;
        uint32_t doff = (uint32_t)(r * 144 + cc * 2);
        cpa16(smem0 + 18432 + doff, g_kh  + kbase + (size_t)(n1 * 64 + r) * HD + cc);
        cpa16(smem0 + 27648 + doff, g_vth + vbase + (size_t)r * SF + n1 * 64 + cc);
    }
    asm volatile("cp.async.commit_group;");

    // Q fragments (2 rowgroups of 16) staged through buffer-2 region
    uint32_t qf[2][4][4];
    {
        fp16* Qst = dsm + 18432;   // buffer 2: 9216 elems = 128x72
        size_t qoff = ((size_t)(b * HH + h) * TT + qb) * HD;
        #pragma unroll
        for (int p = 0; p < 8; p++) {
            int idx = p * 1024 + tid * 8;
            int r = idx >> 6, cc = idx & 63;
            *(uint4*)&Qst[r * 72 + cc] = *(const uint4*)&g_qh[qoff + (size_t)r * HD + cc];
        }
        __syncthreads();
        #pragma unroll
        for (int rg = 0; rg < 2; rg++)
            #pragma unroll
            for (int kc = 0; kc < 4; kc++)
                ldsm4(qf[rg][kc], &Qst[(wid * 32 + rg * 16 + ar) * 72 + kc * 16 + akk]);
    }

    float o[2][8][4];
    float lacc[2][4];
    #pragma unroll
    for (int rg = 0; rg < 2; rg++) {
        #pragma unroll
        for (int dt = 0; dt < 8; dt++)
            #pragma unroll
            for (int e = 0; e < 4; e++) o[rg][dt][e] = 0.0f;
        #pragma unroll
        for (int e = 0; e < 4; e++) lacc[rg][e] = 0.0f;
    }

    int cur = t0, cbuf = 0, abuf = 2;
    #pragma unroll 1
    while (cur < 64) {
        __syncthreads();
        if (ahead < 64) {
            const int sb = ahead * 64;
            const uint32_t sbm = smem0 + abuf * 18432;
            #pragma unroll
            for (int p = 0; p < 4; p++) {
                int idx = p * 1024 + tid * 8;
                int r = idx >> 6, cc = idx & 63;
                uint32_t doff = (uint32_t)(r * 144 + cc * 2);
                cpa16(sbm + doff,        g_kh  + kbase + (size_t)(sb + r) * HD + cc);
                cpa16(sbm + 9216 + doff, g_vth + vbase + (size_t)r * SF + sb + cc);
            }
        }
        asm volatile("cp.async.commit_group;");
        asm volatile("cp.async.wait_group 2;");
        __syncthreads();

        fp16* Ksh = dsm + cbuf * 9216;
        fp16* Vsh = Ksh + 4608;

        float s[2][8][4];
        #pragma unroll
        for (int rg = 0; rg < 2; rg++)
            #pragma unroll
            for (int nt = 0; nt < 8; nt++)
                #pragma unroll
                for (int e = 0; e < 4; e++) s[rg][nt][e] = 0.0f;

        #pragma unroll
        for (int kc = 0; kc < 4; kc++) {
            uint32_t bh[4][4];
            #pragma unroll
            for (int np = 0; np < 4; np++)
                ldsm4(bh[np], &Ksh[(np * 16 + br) * 72 + kc * 16 + bkk]);
            #pragma unroll
            for (int rg = 0; rg < 2; rg++)
                #pragma unroll
                for (int nt = 0; nt < 8; nt++) {
                    int np = nt >> 1, pi = (nt & 1) * 2;
                    mma16816h(s[rg][nt], qf[rg][kc], bh[np][pi], bh[np][pi + 1]);
                }
        }

        // element mask on the two diagonal-straddling tiles
        if (cur < 16 && cur >= 2 * qi) {
            const int sbase = cur * 64;
            #pragma unroll
            for (int rg = 0; rg < 2; rg++)
                #pragma unroll
                for (int nt = 0; nt < 8; nt++)
                    #pragma unroll
                    for (int e = 0; e < 4; e++) {
                        int row = qb + wid * 32 + rg * 16 + g + (e >> 1) * 8;
                        int col = sbase + nt * 8 + tg * 2 + (e & 1);
                        if (col > row) s[rg][nt][e] = NEGINF;
                    }
        }

        #pragma unroll
        for (int rg = 0; rg < 2; rg++)
            #pragma unroll
            for (int nt = 0; nt < 8; nt++) {
                s[rg][nt][0] = ex2f(s[rg][nt][0]);
                s[rg][nt][1] = ex2f(s[rg][nt][1]);
                s[rg][nt][2] = ex2f(s[rg][nt][2]);
                s[rg][nt][3] = ex2f(s[rg][nt][3]);
            }

        #pragma unroll
        for (int kc = 0; kc < 4; kc++) {
            uint32_t vh[4][4];
            #pragma unroll
            for (int np = 0; np < 4; np++)
                ldsm4(vh[np], &Vsh[(np * 16 + br) * 72 + kc * 16 + bkk]);
            #pragma unroll
            for (int rg = 0; rg < 2; rg++) {
                uint32_t ap[4];
                ap[0] = packh(s[rg][2 * kc][0],     s[rg][2 * kc][1]);
                ap[1] = packh(s[rg][2 * kc][2],     s[rg][2 * kc][3]);
                ap[2] = packh(s[rg][2 * kc + 1][0], s[rg][2 * kc + 1][1]);
                ap[3] = packh(s[rg][2 * kc + 1][2], s[rg][2 * kc + 1][3]);
                #pragma unroll
                for (int dt = 0; dt < 8; dt++) {
                    int np = dt >> 1, pi = (dt & 1) * 2;
                    mma16816h(o[rg][dt], ap, vh[np][pi], vh[np][pi + 1]);
                }
                mma16816h(lacc[rg], ap, ones, ones);
            }
        }

        cur = n1;
        n1 = ahead;
        ahead = (n1 < 64 && n1 + 1 < 16 && n1 + 1 >= 2 * qi + 2) ? 16 : n1 + 1;
        if (n1 >= 64) ahead = 64;
        cbuf = (cbuf == 2) ? 0 : cbuf + 1;
        abuf = (abuf == 2) ? 0 : abuf + 1;
    }

    // epilogue: l in quad-leader lane, col 0 of each rowgroup
    #pragma unroll
    for (int rg = 0; rg < 2; rg++) {
        float l0 = __shfl_sync(0xffffffffu, lacc[rg][0], lane & ~3u);
        float l1 = __shfl_sync(0xffffffffu, lacc[rg][2], lane & ~3u);
        float inv0 = 1.0f / l0, inv1 = 1.0f / l1;
        int r0 = qb + wid * 32 + rg * 16 + g;
        int r1 = r0 + 8;
        #pragma unroll
        for (int dt = 0; dt < 8; dt++) {
            int d = dt * 8 + tg * 2;
            size_t off0 = ((size_t)b * TT + r0) * DD + h * HD + d;
            size_t off1 = ((size_t)b * TT + r1) * DD + h * HD + d;
            *reinterpret_cast<fp162*>(&g_ah[off0]) =
                __floats2half2_rn(o[rg][dt][0] * inv0, o[rg][dt][1] * inv0);
            *reinterpret_cast<fp162*>(&g_ah[off1]) =
                __floats2half2_rn(o[rg][dt][2] * inv1, o[rg][dt][3] * inv1);
        }
    }
}

// ---------------------------------------------------------------------------
extern "C" void kernel_launch(void* const* d_in, const int* in_sizes, int n_in,
                              void* d_out, int out_size) {
    const float* x  = (const float*)d_in[0];
    const float* kc = (const float*)d_in[1];
    const float* vc = (const float*)d_in[2];
    const float* bq = (const float*)d_in[4];
    const float* bv = (const float*)d_in[7];
    const float* bo = (const float*)d_in[9];

    float* out  = (float*)d_out;
    float* kout = out + (size_t)BB * TT * DD;
    float* vout = kout + (size_t)BB * SF * DD;

    const int attn_smem = 3 * 18432;   // 55296
    cudaFuncSetAttribute(attn_mma, cudaFuncAttributeMaxDynamicSharedMemorySize, attn_smem);

    conv_xw<<<8192, 256>>>((const float4*)x,
                           (const float*)d_in[3], (const float*)d_in[5],
                           (const float*)d_in[6], (const float*)d_in[8]);          // 0
    gemm_qkv<<<dim3(8, 32, 63), 128>>>(bq, bv, (const float4*)kc, vc, kout, vout); // 1
    attn_mma<<<dim3(8, HH, BB), 128, attn_smem>>>();                               // 2
    gemm_o<<<dim3(8, 32), 128>>>(bo, out);                                         // 3
}

// round 17
// speedup vs baseline: 1.4570x; 1.4570x over previous
#include <cuda_runtime.h>
#include <cuda_fp16.h>
#include <cstdint>

#define BB 4
#define TT 1024
#define DD 1024
#define HH 16
#define HD 64
#define SC 3072
#define SF 4096

typedef __half fp16;
typedef __half2 fp162;

__device__ fp16 g_xh[(size_t)BB * TT * DD];
__device__ fp16 g_wth[4ull * DD * DD];           // transposed weights [w][n][k]
__device__ fp16 g_qh[(size_t)BB * HH * TT * HD]; // q pre-scaled by 0.125*log2(e)
__device__ fp16 g_kh[(size_t)BB * HH * SF * HD];
__device__ fp16 g_vth[(size_t)BB * HH * HD * SF];
__device__ fp16 g_ah[(size_t)BB * TT * DD];      // attn out

__device__ __forceinline__ uint32_t smem_u32(const void* p) {
    return (uint32_t)__cvta_generic_to_shared(p);
}
__device__ __forceinline__ void ldsm4(uint32_t (&r)[4], const void* p) {
    asm volatile("ldmatrix.sync.aligned.m8n8.x4.shared.b16 {%0,%1,%2,%3}, [%4];"
        : "=r"(r[0]), "=r"(r[1]), "=r"(r[2]), "=r"(r[3]) : "r"(smem_u32(p)));
}
__device__ __forceinline__ void mma16816h(float (&c)[4], const uint32_t (&a)[4],
                                          uint32_t b0, uint32_t b1) {
    asm volatile(
        "mma.sync.aligned.m16n8k16.row.col.f32.f16.f16.f32 "
        "{%0,%1,%2,%3},{%4,%5,%6,%7},{%8,%9},{%0,%1,%2,%3};"
        : "+f"(c[0]), "+f"(c[1]), "+f"(c[2]), "+f"(c[3])
        : "r"(a[0]), "r"(a[1]), "r"(a[2]), "r"(a[3]), "r"(b0), "r"(b1));
}
__device__ __forceinline__ uint32_t packh(float x, float y) {
    fp162 t = __floats2half2_rn(x, y);
    return *reinterpret_cast<uint32_t*>(&t);
}
__device__ __forceinline__ float ex2f(float x) {
    float r;
    asm("ex2.approx.f32 %0, %1;" : "=f"(r) : "f"(x));
    return r;
}
__device__ __forceinline__ void cpa16(uint32_t dst, const void* src) {
    asm volatile("cp.async.cg.shared.global [%0], [%1], 16;"
        :: "r"(dst), "l"(__cvta_generic_to_global(src)));
}

// ---------------- merged x + W conversion -------------------------------------
// blocks [0,4096): x -> fp16 ; [4096,8192): weight transpose+convert
__global__ void conv_xw(const float4* __restrict__ x,
                        const float* __restrict__ Wq, const float* __restrict__ Wk,
                        const float* __restrict__ Wv, const float* __restrict__ Wo) {
    __shared__ float t[32][33];
    const int blk = blockIdx.x, tid = threadIdx.x;
    if (blk < 4096) {
        int i = blk * 256 + tid;
        float4 v = x[i];
        reinterpret_cast<fp162*>(g_xh)[2 * i]     = __floats2half2_rn(v.x, v.y);
        reinterpret_cast<fp162*>(g_xh)[2 * i + 1] = __floats2half2_rn(v.z, v.w);
    } else {
        int wb = blk - 4096;
        int z = wb >> 10, rem = wb & 1023;
        int n0 = (rem & 31) * 32, k0 = (rem >> 5) * 32;
        const float* W = (z == 0) ? Wq : (z == 1) ? Wk : (z == 2) ? Wv : Wo;
        int tx = tid & 31, ty = tid >> 5;   // ty 0..7
        #pragma unroll
        for (int r = 0; r < 32; r += 8)
            t[ty + r][tx] = W[(size_t)(k0 + ty + r) * DD + n0 + tx];
        __syncthreads();
        size_t base = (size_t)z * DD * DD;
        #pragma unroll
        for (int r = 0; r < 32; r += 8)
            g_wth[base + (size_t)(n0 + ty + r) * DD + k0 + tx] =
                __float2half_rn(t[tx][ty + r]);
    }
}

// New V rows -> transposed fp16 (reads vout written by gemm_qkv z=2)
__global__ void conv_vt(const float* __restrict__ src, int s0) {
    __shared__ float t[32][33];
    int b = blockIdx.z;
    int h = blockIdx.y >> 1;
    int d0 = (blockIdx.y & 1) * 32;
    int st = blockIdx.x * 32;
    int tx = threadIdx.x, ty = threadIdx.y;
    #pragma unroll
    for (int r = 0; r < 32; r += 8)
        t[ty + r][tx] = src[(size_t)b * SF * DD + (size_t)(st + ty + r) * DD + h * HD + d0 + tx];
    __syncthreads();
    #pragma unroll
    for (int r = 0; r < 32; r += 8) {
        size_t o = ((size_t)(b * HH + h) * HD + d0 + ty + r) * SF + s0 + st + tx;
        g_vth[o] = __float2half_rn(t[tx][ty + r]);
    }
}

// ------- fp16 HMMA GEMM core: 128 thr, 4 warps x (64x64), BK=32, cp.async ----
__device__ __forceinline__ void gemm_fill(fp16 (&As)[2][128][40], fp16 (&Bs)[2][128][40],
                                          const fp16* __restrict__ Ah,
                                          const fp16* __restrict__ Bh,
                                          int bm, int bn, int k0, int buf, int tid) {
    #pragma unroll
    for (int it = 0; it < 4; it++) {
        int idx = it * 128 + tid;        // 0..511
        int r = idx >> 2, cg = (idx & 3) * 8;
        cpa16(smem_u32(&As[buf][r][cg]), Ah + (size_t)(bm + r) * DD + k0 + cg);
        cpa16(smem_u32(&Bs[buf][r][cg]), Bh + (size_t)(bn + r) * DD + k0 + cg);
    }
}

__device__ __forceinline__ void gemm_core(fp16 (&As)[2][128][40], fp16 (&Bs)[2][128][40],
                                          const fp16* __restrict__ Ah,
                                          const fp16* __restrict__ Bh,
                                          int bm, int bn, float (&c)[4][8][4]) {
    const int tid  = threadIdx.x;
    const int lane = tid & 31, wid = tid >> 5;
    const int wm = (wid & 1) * 64, wn = (wid >> 1) * 64;
    const int ar = lane & 15, akk = (lane >> 4) * 8;
    const int br = (lane & 7) + ((lane >> 4) << 3), bkk = ((lane >> 3) & 1) * 8;

    #pragma unroll
    for (int mt = 0; mt < 4; mt++)
        #pragma unroll
        for (int nt = 0; nt < 8; nt++)
            #pragma unroll
            for (int e = 0; e < 4; e++) c[mt][nt][e] = 0.0f;

    gemm_fill(As, Bs, Ah, Bh, bm, bn, 0, 0, tid);
    asm volatile("cp.async.commit_group;");

    int buf = 0;
    #pragma unroll 1
    for (int ch = 0; ch < 32; ch++) {
        __syncthreads();
        if (ch < 31) {
            gemm_fill(As, Bs, Ah, Bh, bm, bn, (ch + 1) << 5, buf ^ 1, tid);
            asm volatile("cp.async.commit_group;");
            asm volatile("cp.async.wait_group 1;");
        } else {
            asm volatile("cp.async.wait_group 0;");
        }
        __syncthreads();

        #pragma unroll
        for (int kc2 = 0; kc2 < 2; kc2++) {
            uint32_t a[4][4], bfr[4][4];
            #pragma unroll
            for (int mt = 0; mt < 4; mt++)
                ldsm4(a[mt], &As[buf][wm + mt * 16 + ar][kc2 * 16 + akk]);
            #pragma unroll
            for (int np = 0; np < 4; np++)
                ldsm4(bfr[np], &Bs[buf][wn + np * 16 + br][kc2 * 16 + bkk]);
            #pragma unroll
            for (int mt = 0; mt < 4; mt++)
                #pragma unroll
                for (int nt = 0; nt < 8; nt++) {
                    int np = nt >> 1, pi = (nt & 1) * 2;
                    mma16816h(c[mt][nt], a[mt], bfr[np][pi], bfr[np][pi + 1]);
                }
        }
        buf ^= 1;
    }
}

// Q scale = 0.125 (hd^-0.5 folded) * log2(e)
#define QSCALE 0.18033688011112042f

// Fused kernel: z<3 = GEMM tiles; z>=3 = cache conversion blocks (overlap).
__global__ __launch_bounds__(128, 2) void gemm_qkv(
    const float* __restrict__ bq, const float* __restrict__ bv,
    const float4* __restrict__ kc4, const float* __restrict__ vc,
    float* __restrict__ kout, float* __restrict__ vout) {
    __shared__ __align__(16) fp16 As[2][128][40];
    __shared__ __align__(16) fp16 Bs[2][128][40];
    __shared__ float t[32][33];

    const int tid = threadIdx.x;

    if (blockIdx.z >= 3) {
        int cid = (int)(blockIdx.z - 3) * 256 + blockIdx.y * 8 + blockIdx.x;
        if (cid < 3072) {
            #pragma unroll
            for (int it = 0; it < 8; it++) {
                int i = cid * 1024 + it * 128 + tid;
                const int per_b = SC * 256;
                int b = i / per_b, r = i - b * per_b;
                int sr = r >> 8, n4 = r & 255;
                float4 v = kc4[i];
                *reinterpret_cast<float4*>(&kout[(((size_t)b * SF + sr) * 256 + n4) * 4]) = v;
                int n = n4 * 4, h = n >> 6, d = n & 63;
                size_t o = ((size_t)(b * HH + h) * SF + sr) * HD + d;
                *reinterpret_cast<fp162*>(&g_kh[o])     = __floats2half2_rn(v.x, v.y);
                *reinterpret_cast<fp162*>(&g_kh[o + 2]) = __floats2half2_rn(v.z, v.w);
            }
        } else {
            int vb = cid - 3072;                 // [0, 12288)
            int xst = vb % 96;
            int y   = (vb / 96) % 32;
            int b   = vb / 3072;
            int st = xst * 32, h = y >> 1, d0 = (y & 1) * 32;
            int tx = tid & 31, ty = tid >> 5;    // ty 0..3
            #pragma unroll
            for (int r = 0; r < 32; r += 4) {
                float v = vc[(size_t)b * SC * DD + (size_t)(st + ty + r) * DD + h * HD + d0 + tx];
                t[ty + r][tx] = v;
                vout[((size_t)b * SF + st + ty + r) * DD + h * HD + d0 + tx] = v;
            }
            __syncthreads();
            #pragma unroll
            for (int r = 0; r < 32; r += 4) {
                size_t o = ((size_t)(b * HH + h) * HD + d0 + ty + r) * SF + st + tx;
                g_vth[o] = __float2half_rn(t[tx][ty + r]);
            }
        }
        return;
    }

    const int z = blockIdx.z;
    const int bm = blockIdx.y * 128, bn = blockIdx.x * 128;
    float c[4][8][4];
    gemm_core(As, Bs, g_xh, g_wth + (size_t)z * DD * DD, bm, bn, c);

    const int lane = tid & 31, wid = tid >> 5;
    const int wm = (wid & 1) * 64, wn = (wid >> 1) * 64;
    const int g = lane >> 2, tg = lane & 3;

    #pragma unroll
    for (int mt = 0; mt < 4; mt++)
        #pragma unroll
        for (int nt = 0; nt < 8; nt++)
            #pragma unroll
            for (int hf = 0; hf < 2; hf++) {
                int row = bm + wm + mt * 16 + g + hf * 8;
                int col = bn + wn + nt * 8 + tg * 2;
                float v0 = c[mt][nt][hf * 2], v1 = c[mt][nt][hf * 2 + 1];
                int b = row >> 10, tt = row & 1023;
                int h = col >> 6, d = col & 63;
                if (z == 0) {
                    v0 = (v0 + bq[col]) * QSCALE;
                    v1 = (v1 + bq[col + 1]) * QSCALE;
                    size_t o = ((size_t)(b * HH + h) * TT + tt) * HD + d;
                    *reinterpret_cast<fp162*>(&g_qh[o]) = __floats2half2_rn(v0, v1);
                } else if (z == 1) {
                    *(float2*)&kout[((size_t)b * SF + SC + tt) * DD + col] = make_float2(v0, v1);
                    size_t o = ((size_t)(b * HH + h) * SF + SC + tt) * HD + d;
                    *reinterpret_cast<fp162*>(&g_kh[o]) = __floats2half2_rn(v0, v1);
                } else {
                    v0 += bv[col]; v1 += bv[col + 1];
                    *(float2*)&vout[((size_t)b * SF + SC + tt) * DD + col] = make_float2(v0, v1);
                }
            }
}

__global__ __launch_bounds__(128, 2) void gemm_o(const float* __restrict__ bo,
                                                 float* __restrict__ out) {
    __shared__ __align__(16) fp16 As[2][128][40];
    __shared__ __align__(16) fp16 Bs[2][128][40];

    const int bm = blockIdx.y * 128, bn = blockIdx.x * 128;
    float c[4][8][4];
    gemm_core(As, Bs, g_ah, g_wth + 3ull * DD * DD, bm, bn, c);

    const int tid = threadIdx.x, lane = tid & 31, wid = tid >> 5;
    const int wm = (wid & 1) * 64, wn = (wid >> 1) * 64;
    const int g = lane >> 2, tg = lane & 3;

    #pragma unroll
    for (int mt = 0; mt < 4; mt++)
        #pragma unroll
        for (int nt = 0; nt < 8; nt++)
            #pragma unroll
            for (int hf = 0; hf < 2; hf++) {
                int row = bm + wm + mt * 16 + g + hf * 8;
                int col = bn + wn + nt * 8 + tg * 2;
                float v0 = c[mt][nt][hf * 2] + bo[col];
                float v1 = c[mt][nt][hf * 2 + 1] + bo[col + 1];
                *(float2*)&out[(size_t)row * DD + col] = make_float2(v0, v1);
            }
}

// -------- FlashAttention: 128-row q tiles, 4 warps x 32 rows, 3-stage pipe ---
// dynamic smem: 3 buffers x (Ksh,Vsh) x [64][72] fp16 = 55296 B
__global__ __launch_bounds__(128) void attn_mma() {
    extern __shared__ __align__(16) fp16 dsm[];

    const int tid = threadIdx.x, lane = tid & 31, wid = tid >> 5;
    const int qi = 7 - blockIdx.x;           // heavy tiles first (qi 0..7)
    const int h = blockIdx.y, b = blockIdx.z;
    const int qb = qi * 128;
    const int g = lane >> 2, tg = lane & 3;
    const int ar = lane & 15, akk = (lane >> 4) * 8;
    const int br = (lane & 7) + ((lane >> 4) << 3), bkk = ((lane >> 3) & 1) * 8;
    const float NEGINF = __int_as_float(0xff800000);
    const uint32_t ones = (lane < 4) ? 0x3C003C00u : 0u;

    const size_t kbase = (size_t)(b * HH + h) * SF * HD;
    const size_t vbase = (size_t)(b * HH + h) * HD * SF;
    const uint32_t smem0 = smem_u32(dsm);

    // tile iterator with mask-skip: skip si in [2qi+2, 16)
    int t0 = 0;
    int n1 = (1 < 16 && 1 >= 2 * qi + 2) ? 16 : 1;
    int ahead = (n1 + 1 < 16 && n1 + 1 >= 2 * qi + 2) ? 16 : n1 + 1;

    #pragma unroll
    for (int p = 0; p < 4; p++) {
        int idx = p * 1024 + tid * 8;
        int r = idx >> 6, cc = idx & 63;
        uint32_t doff = (uint32_t)(r * 144 + cc * 2);
        cpa16(smem0 + doff,        g_kh  + kbase + (size_t)(t0 * 64 + r) * HD + cc);
        cpa16(smem0 + 9216 + doff, g_vth + vbase + (size_t)r * SF + t0 * 64 + cc);
    }
    asm volatile("cp.async.commit_group;");
    #pragma unroll
    for (int p = 0; p < 4; p++) {
        int idx = p * 1024 + tid * 8;
        int r = idx >> 6, cc = idx & 63;
        uint32_t doff = (uint32_t)(r * 144 + cc * 2);
        cpa16(smem0 + 18432 + doff, g_kh  + kbase + (size_t)(n1 * 64 + r) * HD + cc);
        cpa16(smem0 + 27648 + doff, g_vth + vbase + (size_t)r * SF + n1 * 64 + cc);
    }
    asm volatile("cp.async.commit_group;");

    // Q fragments (2 rowgroups of 16) staged through buffer-2 region
    uint32_t qf[2][4][4];
    {
        fp16* Qst = dsm + 18432;   // buffer 2: 9216 elems = 128x72
        size_t qoff = ((size_t)(b * HH + h) * TT + qb) * HD;
        #pragma unroll
        for (int p = 0; p < 8; p++) {
            int idx = p * 1024 + tid * 8;
            int r = idx >> 6, cc = idx & 63;
            *(uint4*)&Qst[r * 72 + cc] = *(const uint4*)&g_qh[qoff + (size_t)r * HD + cc];
        }
        __syncthreads();
        #pragma unroll
        for (int rg = 0; rg < 2; rg++)
            #pragma unroll
            for (int kc = 0; kc < 4; kc++)
                ldsm4(qf[rg][kc], &Qst[(wid * 32 + rg * 16 + ar) * 72 + kc * 16 + akk]);
    }

    float o[2][8][4];
    float lacc[2][4];
    #pragma unroll
    for (int rg = 0; rg < 2; rg++) {
        #pragma unroll
        for (int dt = 0; dt < 8; dt++)
            #pragma unroll
            for (int e = 0; e < 4; e++) o[rg][dt][e] = 0.0f;
        #pragma unroll
        for (int e = 0; e < 4; e++) lacc[rg][e] = 0.0f;
    }

    int cur = t0, cbuf = 0, abuf = 2;
    #pragma unroll 1
    while (cur < 64) {
        __syncthreads();
        if (ahead < 64) {
            const int sb = ahead * 64;
            const uint32_t sbm = smem0 + abuf * 18432;
            #pragma unroll
            for (int p = 0; p < 4; p++) {
                int idx = p * 1024 + tid * 8;
                int r = idx >> 6, cc = idx & 63;
                uint32_t doff = (uint32_t)(r * 144 + cc * 2);
                cpa16(sbm + doff,        g_kh  + kbase + (size_t)(sb + r) * HD + cc);
                cpa16(sbm + 9216 + doff, g_vth + vbase + (size_t)r * SF + sb + cc);
            }
        }
        asm volatile("cp.async.commit_group;");
        asm volatile("cp.async.wait_group 2;");
        __syncthreads();

        fp16* Ksh = dsm + cbuf * 9216;
        fp16* Vsh = Ksh + 4608;

        float s[2][8][4];
        #pragma unroll
        for (int rg = 0; rg < 2; rg++)
            #pragma unroll
            for (int nt = 0; nt < 8; nt++)
                #pragma unroll
                for (int e = 0; e < 4; e++) s[rg][nt][e] = 0.0f;

        #pragma unroll
        for (int kc = 0; kc < 4; kc++) {
            uint32_t bh[4][4];
            #pragma unroll
            for (int np = 0; np < 4; np++)
                ldsm4(bh[np], &Ksh[(np * 16 + br) * 72 + kc * 16 + bkk]);
            #pragma unroll
            for (int rg = 0; rg < 2; rg++)
                #pragma unroll
                for (int nt = 0; nt < 8; nt++) {
                    int np = nt >> 1, pi = (nt & 1) * 2;
                    mma16816h(s[rg][nt], qf[rg][kc], bh[np][pi], bh[np][pi + 1]);
                }
        }

        // element mask on the two diagonal-straddling tiles
        if (cur < 16 && cur >= 2 * qi) {
            const int sbase = cur * 64;
            #pragma unroll
            for (int rg = 0; rg < 2; rg++)
                #pragma unroll
                for (int nt = 0; nt < 8; nt++)
                    #pragma unroll
                    for (int e = 0; e < 4; e++) {
                        int row = qb + wid * 32 + rg * 16 + g + (e >> 1) * 8;
                        int col = sbase + nt * 8 + tg * 2 + (e & 1);
                        if (col > row) s[rg][nt][e] = NEGINF;
                    }
        }

        #pragma unroll
        for (int rg = 0; rg < 2; rg++)
            #pragma unroll
            for (int nt = 0; nt < 8; nt++) {
                s[rg][nt][0] = ex2f(s[rg][nt][0]);
                s[rg][nt][1] = ex2f(s[rg][nt][1]);
                s[rg][nt][2] = ex2f(s[rg][nt][2]);
                s[rg][nt][3] = ex2f(s[rg][nt][3]);
            }

        #pragma unroll
        for (int kc = 0; kc < 4; kc++) {
            uint32_t vh[4][4];
            #pragma unroll
            for (int np = 0; np < 4; np++)
                ldsm4(vh[np], &Vsh[(np * 16 + br) * 72 + kc * 16 + bkk]);
            #pragma unroll
            for (int rg = 0; rg < 2; rg++) {
                uint32_t ap[4];
                ap[0] = packh(s[rg][2 * kc][0],     s[rg][2 * kc][1]);
                ap[1] = packh(s[rg][2 * kc][2],     s[rg][2 * kc][3]);
                ap[2] = packh(s[rg][2 * kc + 1][0], s[rg][2 * kc + 1][1]);
                ap[3] = packh(s[rg][2 * kc + 1][2], s[rg][2 * kc + 1][3]);
                #pragma unroll
                for (int dt = 0; dt < 8; dt++) {
                    int np = dt >> 1, pi = (dt & 1) * 2;
                    mma16816h(o[rg][dt], ap, vh[np][pi], vh[np][pi + 1]);
                }
                mma16816h(lacc[rg], ap, ones, ones);
            }
        }

        cur = n1;
        n1 = ahead;
        ahead = (n1 < 64 && n1 + 1 < 16 && n1 + 1 >= 2 * qi + 2) ? 16 : n1 + 1;
        if (n1 >= 64) ahead = 64;
        cbuf = (cbuf == 2) ? 0 : cbuf + 1;
        abuf = (abuf == 2) ? 0 : abuf + 1;
    }

    // epilogue: l in quad-leader lane, col 0 of each rowgroup
    #pragma unroll
    for (int rg = 0; rg < 2; rg++) {
        float l0 = __shfl_sync(0xffffffffu, lacc[rg][0], lane & ~3u);
        float l1 = __shfl_sync(0xffffffffu, lacc[rg][2], lane & ~3u);
        float inv0 = 1.0f / l0, inv1 = 1.0f / l1;
        int r0 = qb + wid * 32 + rg * 16 + g;
        int r1 = r0 + 8;
        #pragma unroll
        for (int dt = 0; dt < 8; dt++) {
            int d = dt * 8 + tg * 2;
            size_t off0 = ((size_t)b * TT + r0) * DD + h * HD + d;
            size_t off1 = ((size_t)b * TT + r1) * DD + h * HD + d;
            *reinterpret_cast<fp162*>(&g_ah[off0]) =
                __floats2half2_rn(o[rg][dt][0] * inv0, o[rg][dt][1] * inv0);
            *reinterpret_cast<fp162*>(&g_ah[off1]) =
                __floats2half2_rn(o[rg][dt][2] * inv1, o[rg][dt][3] * inv1);
        }
    }
}

// ---------------------------------------------------------------------------
extern "C" void kernel_launch(void* const* d_in, const int* in_sizes, int n_in,
                              void* d_out, int out_size) {
    const float* x  = (const float*)d_in[0];
    const float* kc = (const float*)d_in[1];
    const float* vc = (const float*)d_in[2];
    const float* bq = (const float*)d_in[4];
    const float* bv = (const float*)d_in[7];
    const float* bo = (const float*)d_in[9];

    float* out  = (float*)d_out;
    float* kout = out + (size_t)BB * TT * DD;
    float* vout = kout + (size_t)BB * SF * DD;

    const int attn_smem = 3 * 18432;   // 55296
    cudaFuncSetAttribute(attn_mma, cudaFuncAttributeMaxDynamicSharedMemorySize, attn_smem);

    conv_xw<<<8192, 256>>>((const float4*)x,
                           (const float*)d_in[3], (const float*)d_in[5],
                           (const float*)d_in[6], (const float*)d_in[8]);          // 0
    gemm_qkv<<<dim3(8, 32, 63), 128>>>(bq, bv, (const float4*)kc, vc, kout, vout); // 1
    conv_vt<<<dim3(16, HH * 2, BB), dim3(32, 8)>>>(vout + (size_t)SC * DD, SC);    // 2
    conv_vt<<<dim3(16, HH * 2, BB), dim3(32, 8)>>>(vout + (size_t)(SC + 512) * DD,
                                                   SC + 512);                      // 3
    attn_mma<<<dim3(8, HH, BB), 128, attn_smem>>>();                               // 4
    gemm_o<<<dim3(8, 32), 128>>>(bo, out);                                         // 5
}